// round 8
// baseline (speedup 1.0000x reference)
#include <cuda_runtime.h>
#include <math.h>
#include <float.h>
#include <stdint.h>
#include <cuda_fp16.h>

#define KCOMP 32
#define DDIM  128
#define LDIM  4
#define TPB   256
#define ROWS_TILE 128

// smem byte offsets (~53KB total)
#define SM_W   0        // weights: 192 rows x 256B (fp16) = 49152
#define SM_C   49152    // cst[32] + bm[4][32] floats = 640
#define SM_P   49792    // sP: 2 buffers x 256 float2 = 4096
#define SMEM_TOTAL 53888

// ---- device globals -------------------------------------------------------
__device__ uint4  g_Wh[192 * 16];      // fp16 weights, row n: 128 halves
__device__ float  g_cst[KCOMP];
__device__ float4 g_bm[KCOMP];

// ---- helpers --------------------------------------------------------------
__device__ __forceinline__ uint32_t h2pack(float a, float b) {
    __half2 h = __floats2half2_rn(a, b);
    return *(uint32_t*)&h;
}
__device__ __forceinline__ uint32_t smem_u32(const void* p) {
    uint32_t a;
    asm("{ .reg .u64 t; cvta.to.shared.u64 t, %1; cvt.u32.u64 %0, t; }" : "=r"(a) : "l"(p));
    return a;
}
__device__ __forceinline__ void mma16816(float c[4], const uint32_t a[4],
                                         uint32_t b0, uint32_t b1) {
    asm volatile(
        "mma.sync.aligned.m16n8k16.row.col.f32.f16.f16.f32 "
        "{%0,%1,%2,%3}, {%4,%5,%6,%7}, {%8,%9}, {%0,%1,%2,%3};"
        : "+f"(c[0]), "+f"(c[1]), "+f"(c[2]), "+f"(c[3])
        : "r"(a[0]), "r"(a[1]), "r"(a[2]), "r"(a[3]), "r"(b0), "r"(b1));
}
__device__ __forceinline__ void ldsm4(uint32_t r[4], uint32_t addr) {
    asm volatile("ldmatrix.sync.aligned.m8n8.x4.shared.b16 {%0,%1,%2,%3}, [%4];"
        : "=r"(r[0]), "=r"(r[1]), "=r"(r[2]), "=r"(r[3]) : "r"(addr));
}
__device__ __forceinline__ uint32_t sq2(uint32_t a) {
    __half2 h = *(__half2*)&a;
    h = __hmul2(h, h);
    return *(uint32_t*)&h;
}

// ---------------------------------------------------------------------------
// Stage A: per-component precompute. 32 blocks x 1 warp; fp32 throughout.
// ---------------------------------------------------------------------------
__global__ void mfa_precompute(const float* __restrict__ MU,
                               const float* __restrict__ A,
                               const float* __restrict__ Dm,
                               const float* __restrict__ PI)
{
    const int k    = blockIdx.x;
    const int lane = threadIdx.x;

    float s[22];
#pragma unroll
    for (int j = 0; j < 22; j++) s[j] = 0.f;

#pragma unroll
    for (int i = 0; i < 4; i++) {
        const int d = lane + 32 * i;
        const float Dv = Dm[k * DDIM + d];
        const float iD = 1.0f / (Dv * Dv);
        const float mu = MU[k * DDIM + d];
        float a[LDIM], B[LDIM];
#pragma unroll
        for (int l = 0; l < LDIM; l++) {
            a[l] = A[(k * DDIM + d) * LDIM + l];
            B[l] = iD * a[l];
        }
        int idx = 0;
#pragma unroll
        for (int l = 0; l < LDIM; l++)
#pragma unroll
            for (int m = 0; m < LDIM; m++)
                s[idx++] += a[l] * B[m];
#pragma unroll
        for (int m = 0; m < LDIM; m++)
            s[idx++] += mu * B[m];
        s[20] += iD * mu * mu;
        s[21] += 2.0f * logf(Dv);
    }

#pragma unroll
    for (int j = 0; j < 22; j++)
#pragma unroll
        for (int o = 16; o; o >>= 1)
            s[j] += __shfl_xor_sync(0xffffffffu, s[j], o);

    float Lm[LDIM][LDIM], bmu[LDIM];
#pragma unroll
    for (int l = 0; l < LDIM; l++)
#pragma unroll
        for (int m = 0; m < LDIM; m++)
            Lm[l][m] = s[l * LDIM + m] + (l == m ? 1.0f : 0.0f);
#pragma unroll
    for (int m = 0; m < LDIM; m++) bmu[m] = s[16 + m];
    const float tc  = s[20];
    const float sld = s[21];

    float G[LDIM][LDIM] = {};
#pragma unroll
    for (int i = 0; i < LDIM; i++) {
#pragma unroll
        for (int j = 0; j <= i; j++) {
            float v = Lm[i][j];
#pragma unroll
            for (int p = 0; p < LDIM; p++)
                if (p < j) v -= G[i][p] * G[j][p];
            if (i == j) G[i][i] = sqrtf(v);
            else        G[i][j] = v / G[j][j];
        }
    }
    float logdetL = 0.f;
#pragma unroll
    for (int i = 0; i < LDIM; i++) logdetL += 2.0f * logf(G[i][i]);

    float U[LDIM][LDIM] = {};
#pragma unroll
    for (int j = 0; j < LDIM; j++) {
        U[j][j] = 1.0f / G[j][j];
#pragma unroll
        for (int i = 0; i < LDIM; i++) {
            if (i > j) {
                float v = 0.f;
#pragma unroll
                for (int p = 0; p < LDIM; p++)
                    if (p >= j && p < i) v += G[i][p] * U[p][j];
                U[i][j] = -v / G[i][i];
            }
        }
    }

    if (lane == 0) {
        const float LOG2PI = 1.8378770664093454835606594728112f;
        g_cst[k] = PI[k] - 0.5f * ((float)DDIM * LOG2PI + logdetL + sld + tc);
        float bp[LDIM];
#pragma unroll
        for (int l = 0; l < LDIM; l++) {
            float v = 0.f;
#pragma unroll
            for (int m = 0; m <= l; m++) v += U[l][m] * bmu[m];
            bp[l] = v;
        }
        g_bm[k] = make_float4(bp[0], bp[1], bp[2], bp[3]);
    }

    __half* Wh = (__half*)g_Wh;
#pragma unroll
    for (int i = 0; i < 4; i++) {
        const int d = lane + 32 * i;
        const float Dv = Dm[k * DDIM + d];
        const float iD = 1.0f / (Dv * Dv);
        const float mu = MU[k * DDIM + d];
        float B[LDIM];
#pragma unroll
        for (int l = 0; l < LDIM; l++)
            B[l] = iD * A[(k * DDIM + d) * LDIM + l];
        float Bp[LDIM];
#pragma unroll
        for (int l = 0; l < LDIM; l++) {
            float v = 0.f;
#pragma unroll
            for (int m = 0; m <= l; m++) v += U[l][m] * B[m];
            Bp[l] = v;
        }
        Wh[(size_t)k * DDIM + d] = __float2half_rn(iD * mu);
#pragma unroll
        for (int j = 0; j < LDIM; j++)
            Wh[(size_t)(32 + 32 * j + k) * DDIM + d] = __float2half_rn(Bp[j]);
        Wh[(size_t)(160 + k) * DDIM + d] = __float2half_rn(iD);
    }
}

// ---------------------------------------------------------------------------
// Stage B: persistent mma.sync kernel. A-fragments loaded directly from gmem
// into registers (no x smem tile, no load barrier). B via ldsm from smem.
// 8 warps: (wm rows-32) x (wk comp-16). One __syncthreads per tile.
// ---------------------------------------------------------------------------
__global__ void __launch_bounds__(TPB, 2)
mfa_mma(const float* __restrict__ x, float* __restrict__ out, int N, int ntiles)
{
    extern __shared__ char smc[];
    const int tid  = threadIdx.x;
    const int lane = tid & 31;
    const int w    = tid >> 5;
    const int wm   = w & 3;         // row group (32 rows)
    const int wk   = w >> 2;        // component half (16 comps)
    const int qr   = lane >> 2;     // 0..7
    const int qc   = lane & 3;      // 0..3
    const int rin  = lane & 7;
    const int mat  = lane >> 3;     // 0..3

    const uint32_t sb = smem_u32(smc);

    // ---- load weights to smem once (persistent) ---------------------------
    for (int i = tid; i < 192 * 16; i += TPB) {
        const int r = i >> 4, s = i & 15;
        uint4 v = g_Wh[i];
        *(uint4*)(smc + SM_W + r * 256 + ((s ^ (r & 7)) << 4)) = v;
    }
    {
        float* c = (float*)(smc + SM_C);
        if (tid < 32) {
            c[tid] = g_cst[tid];
            float4 b = g_bm[tid];
            c[32 + tid] = b.x; c[64 + tid] = b.y;
            c[96 + tid] = b.z; c[128 + tid] = b.w;
        }
    }
    __syncthreads();

    const float* cst = (const float*)(smc + SM_C);
    const uint32_t b_pre = sb + SM_W
        + (uint32_t)(wk * 16 + (mat >> 1) * 8 + rin) * 256u;
    const float2* xp = (const float2*)x;

    for (int tile = blockIdx.x; tile < ntiles; tile += gridDim.x) {
        const int row0 = tile * ROWS_TILE;

        // row base pointers for this thread's A-fragment rows (clamped)
        const float2* rp[4];
#pragma unroll
        for (int j = 0; j < 4; j++) {
            int r = row0 + wm * 32 + j * 8 + qr;
            r = r < N ? r : N - 1;
            rp[j] = xp + (size_t)r * 64 + qc;
        }

        // ---- GEMM: acc[mt][g][hi][4]; g: 0=s2, 1..4=z, 5=s1 ---------------
        float acc[2][6][2][4];
#pragma unroll
        for (int mt = 0; mt < 2; mt++)
#pragma unroll
            for (int g = 0; g < 6; g++)
#pragma unroll
                for (int hi = 0; hi < 2; hi++)
#pragma unroll
                    for (int e = 0; e < 4; e++) acc[mt][g][hi][e] = 0.f;

#pragma unroll
        for (int ch = 0; ch < 8; ch++) {
            const int c0 = 8 * ch;    // float2 column index (=16 floats/chunk)

            // A fragments straight from gmem (L1 catches the wk-pair reuse)
            const float2 p00 = __ldg(rp[0] + c0);
            const float2 p01 = __ldg(rp[0] + c0 + 4);
            const float2 p10 = __ldg(rp[1] + c0);
            const float2 p11 = __ldg(rp[1] + c0 + 4);
            const float2 p20 = __ldg(rp[2] + c0);
            const float2 p21 = __ldg(rp[2] + c0 + 4);
            const float2 p30 = __ldg(rp[3] + c0);
            const float2 p31 = __ldg(rp[3] + c0 + 4);

            uint32_t ax[2][4];
            ax[0][0] = h2pack(p00.x, p00.y);
            ax[0][1] = h2pack(p10.x, p10.y);
            ax[0][2] = h2pack(p01.x, p01.y);
            ax[0][3] = h2pack(p11.x, p11.y);
            ax[1][0] = h2pack(p20.x, p20.y);
            ax[1][1] = h2pack(p30.x, p30.y);
            ax[1][2] = h2pack(p21.x, p21.y);
            ax[1][3] = h2pack(p31.x, p31.y);

            const uint32_t xb = (((uint32_t)(ch * 2 + (mat & 1))) ^ (uint32_t)rin) << 4;

#pragma unroll
            for (int g = 0; g < 5; g++) {
                uint32_t b[4];
                ldsm4(b, b_pre + (uint32_t)g * 8192u + xb);
                mma16816(acc[0][g][0], ax[0], b[0], b[1]);
                mma16816(acc[1][g][0], ax[1], b[0], b[1]);
                mma16816(acc[0][g][1], ax[0], b[2], b[3]);
                mma16816(acc[1][g][1], ax[1], b[2], b[3]);
            }

            uint32_t aq[2][4];
#pragma unroll
            for (int j = 0; j < 4; j++) {
                aq[0][j] = sq2(ax[0][j]);
                aq[1][j] = sq2(ax[1][j]);
            }
            {
                uint32_t b[4];
                ldsm4(b, b_pre + 5u * 8192u + xb);
                mma16816(acc[0][5][0], aq[0], b[0], b[1]);
                mma16816(acc[1][5][0], aq[1], b[0], b[1]);
                mma16816(acc[0][5][1], aq[0], b[2], b[3]);
                mma16816(acc[1][5][1], aq[1], b[2], b[3]);
            }
        }

        // ---- partial epilogue: common max, then exp ------------------------
        float2* sP = (float2*)(smc + SM_P + (tile & 1) * 2048);
#pragma unroll
        for (int mt = 0; mt < 2; mt++) {
#pragma unroll
            for (int h = 0; h < 2; h++) {
                float ll[4];
#pragma unroll
                for (int hi = 0; hi < 2; hi++) {
#pragma unroll
                    for (int p = 0; p < 2; p++) {
                        const int k = wk * 16 + hi * 8 + 2 * qc + p;
                        const int e = 2 * h + p;
                        float v = cst[k] + acc[mt][0][hi][e]
                                - 0.5f * acc[mt][5][hi][e];
#pragma unroll
                        for (int jj = 0; jj < 4; jj++) {
                            const float z = acc[mt][1 + jj][hi][e]
                                          - cst[32 + 32 * jj + k];
                            v = fmaf(0.5f * z, z, v);
                        }
                        ll[hi * 2 + p] = v;
                    }
                }
                float mx = fmaxf(fmaxf(ll[0], ll[1]), fmaxf(ll[2], ll[3]));
#pragma unroll
                for (int off = 1; off <= 2; off <<= 1)
                    mx = fmaxf(mx, __shfl_xor_sync(0xffffffffu, mx, off));
                float sum = __expf(ll[0] - mx) + __expf(ll[1] - mx)
                          + __expf(ll[2] - mx) + __expf(ll[3] - mx);
#pragma unroll
                for (int off = 1; off <= 2; off <<= 1)
                    sum += __shfl_xor_sync(0xffffffffu, sum, off);

                if (qc == 0)
                    sP[wk * 128 + wm * 32 + mt * 16 + qr + 8 * h]
                        = make_float2(mx, sum);
            }
        }
        __syncthreads();

        // ---- combine the two component halves, write out ------------------
        if (tid < 128) {
            const float2 a = sP[tid];
            const float2 b = sP[128 + tid];
            const float m = fmaxf(a.x, b.x);
            const float s = a.y * __expf(a.x - m) + b.y * __expf(b.x - m);
            const int row = row0 + tid;
            if (row < N) out[row] = m + __logf(s);
        }
    }
}

// ---------------------------------------------------------------------------
extern "C" void kernel_launch(void* const* d_in, const int* in_sizes, int n_in,
                              void* d_out, int out_size)
{
    const float* x  = (const float*)d_in[0];
    const float* MU = (const float*)d_in[1];
    const float* A  = (const float*)d_in[2];
    const float* Dm = (const float*)d_in[3];
    const float* PI = (const float*)d_in[4];
    float* out = (float*)d_out;

    const int N = in_sizes[0] / DDIM;
    const int ntiles = (N + ROWS_TILE - 1) / ROWS_TILE;

    int nsm = 148;
    cudaDeviceGetAttribute(&nsm, cudaDevAttrMultiProcessorCount, 0);
    if (nsm <= 0) nsm = 148;
    int grid = 2 * nsm;
    if (grid > ntiles) grid = ntiles;

    cudaFuncSetAttribute(mfa_mma, cudaFuncAttributeMaxDynamicSharedMemorySize,
                         SMEM_TOTAL);

    mfa_precompute<<<KCOMP, 32>>>(MU, A, Dm, PI);
    mfa_mma<<<grid, TPB, SMEM_TOTAL>>>(x, out, N, ntiles);
}

// round 9
// speedup vs baseline: 1.3149x; 1.3149x over previous
#include <cuda_runtime.h>
#include <math.h>
#include <float.h>
#include <stdint.h>
#include <cuda_fp16.h>

#define KCOMP 32
#define DDIM  128
#define LDIM  4
#define TPB   512
#define ROWS_TILE 128

// smem byte offsets (~117KB, 1 CTA/SM, 512 threads)
#define SM_W   0         // weights: 192 rows x 256B (fp16) = 49152
#define SM_X0  49152     // x tile buffer 0: 128 x 256B = 32768
#define SM_X1  81920     // x tile buffer 1
#define SM_C   114688    // cst[32] + bm[4][32] floats = 640
#define SM_P   115328    // sP: 2 x 256 float2 = 4096
#define SMEM_TOTAL 119424

// ---- device globals -------------------------------------------------------
__device__ uint4  g_Wh[192 * 16];      // fp16 weights, row n: 128 halves
__device__ float  g_cst[KCOMP];
__device__ float4 g_bm[KCOMP];

// ---- helpers --------------------------------------------------------------
__device__ __forceinline__ uint32_t h2pack(float a, float b) {
    __half2 h = __floats2half2_rn(a, b);
    return *(uint32_t*)&h;
}
__device__ __forceinline__ uint32_t smem_u32(const void* p) {
    uint32_t a;
    asm("{ .reg .u64 t; cvta.to.shared.u64 t, %1; cvt.u32.u64 %0, t; }" : "=r"(a) : "l"(p));
    return a;
}
__device__ __forceinline__ void mma16816(float c[4], const uint32_t a[4],
                                         uint32_t b0, uint32_t b1) {
    asm volatile(
        "mma.sync.aligned.m16n8k16.row.col.f32.f16.f16.f32 "
        "{%0,%1,%2,%3}, {%4,%5,%6,%7}, {%8,%9}, {%0,%1,%2,%3};"
        : "+f"(c[0]), "+f"(c[1]), "+f"(c[2]), "+f"(c[3])
        : "r"(a[0]), "r"(a[1]), "r"(a[2]), "r"(a[3]), "r"(b0), "r"(b1));
}
__device__ __forceinline__ void ldsm4(uint32_t r[4], uint32_t addr) {
    asm volatile("ldmatrix.sync.aligned.m8n8.x4.shared.b16 {%0,%1,%2,%3}, [%4];"
        : "=r"(r[0]), "=r"(r[1]), "=r"(r[2]), "=r"(r[3]) : "r"(addr));
}
__device__ __forceinline__ uint32_t sq2(uint32_t a) {
    __half2 h = *(__half2*)&a;
    h = __hmul2(h, h);
    return *(uint32_t*)&h;
}

// ---------------------------------------------------------------------------
// Stage A: per-component precompute. 32 blocks x 1 warp; fp32 throughout.
// s1 weight rows now carry -0.5*iD (fold into the s2 accumulator).
// ---------------------------------------------------------------------------
__global__ void mfa_precompute(const float* __restrict__ MU,
                               const float* __restrict__ A,
                               const float* __restrict__ Dm,
                               const float* __restrict__ PI)
{
    const int k    = blockIdx.x;
    const int lane = threadIdx.x;

    float s[22];
#pragma unroll
    for (int j = 0; j < 22; j++) s[j] = 0.f;

#pragma unroll
    for (int i = 0; i < 4; i++) {
        const int d = lane + 32 * i;
        const float Dv = Dm[k * DDIM + d];
        const float iD = 1.0f / (Dv * Dv);
        const float mu = MU[k * DDIM + d];
        float a[LDIM], B[LDIM];
#pragma unroll
        for (int l = 0; l < LDIM; l++) {
            a[l] = A[(k * DDIM + d) * LDIM + l];
            B[l] = iD * a[l];
        }
        int idx = 0;
#pragma unroll
        for (int l = 0; l < LDIM; l++)
#pragma unroll
            for (int m = 0; m < LDIM; m++)
                s[idx++] += a[l] * B[m];
#pragma unroll
        for (int m = 0; m < LDIM; m++)
            s[idx++] += mu * B[m];
        s[20] += iD * mu * mu;
        s[21] += 2.0f * logf(Dv);
    }

#pragma unroll
    for (int j = 0; j < 22; j++)
#pragma unroll
        for (int o = 16; o; o >>= 1)
            s[j] += __shfl_xor_sync(0xffffffffu, s[j], o);

    float Lm[LDIM][LDIM], bmu[LDIM];
#pragma unroll
    for (int l = 0; l < LDIM; l++)
#pragma unroll
        for (int m = 0; m < LDIM; m++)
            Lm[l][m] = s[l * LDIM + m] + (l == m ? 1.0f : 0.0f);
#pragma unroll
    for (int m = 0; m < LDIM; m++) bmu[m] = s[16 + m];
    const float tc  = s[20];
    const float sld = s[21];

    float G[LDIM][LDIM] = {};
#pragma unroll
    for (int i = 0; i < LDIM; i++) {
#pragma unroll
        for (int j = 0; j <= i; j++) {
            float v = Lm[i][j];
#pragma unroll
            for (int p = 0; p < LDIM; p++)
                if (p < j) v -= G[i][p] * G[j][p];
            if (i == j) G[i][i] = sqrtf(v);
            else        G[i][j] = v / G[j][j];
        }
    }
    float logdetL = 0.f;
#pragma unroll
    for (int i = 0; i < LDIM; i++) logdetL += 2.0f * logf(G[i][i]);

    float U[LDIM][LDIM] = {};
#pragma unroll
    for (int j = 0; j < LDIM; j++) {
        U[j][j] = 1.0f / G[j][j];
#pragma unroll
        for (int i = 0; i < LDIM; i++) {
            if (i > j) {
                float v = 0.f;
#pragma unroll
                for (int p = 0; p < LDIM; p++)
                    if (p >= j && p < i) v += G[i][p] * U[p][j];
                U[i][j] = -v / G[i][i];
            }
        }
    }

    if (lane == 0) {
        const float LOG2PI = 1.8378770664093454835606594728112f;
        g_cst[k] = PI[k] - 0.5f * ((float)DDIM * LOG2PI + logdetL + sld + tc);
        float bp[LDIM];
#pragma unroll
        for (int l = 0; l < LDIM; l++) {
            float v = 0.f;
#pragma unroll
            for (int m = 0; m <= l; m++) v += U[l][m] * bmu[m];
            bp[l] = v;
        }
        g_bm[k] = make_float4(bp[0], bp[1], bp[2], bp[3]);
    }

    __half* Wh = (__half*)g_Wh;
#pragma unroll
    for (int i = 0; i < 4; i++) {
        const int d = lane + 32 * i;
        const float Dv = Dm[k * DDIM + d];
        const float iD = 1.0f / (Dv * Dv);
        const float mu = MU[k * DDIM + d];
        float B[LDIM];
#pragma unroll
        for (int l = 0; l < LDIM; l++)
            B[l] = iD * A[(k * DDIM + d) * LDIM + l];
        float Bp[LDIM];
#pragma unroll
        for (int l = 0; l < LDIM; l++) {
            float v = 0.f;
#pragma unroll
            for (int m = 0; m <= l; m++) v += U[l][m] * B[m];
            Bp[l] = v;
        }
        Wh[(size_t)k * DDIM + d] = __float2half_rn(iD * mu);
#pragma unroll
        for (int j = 0; j < LDIM; j++)
            Wh[(size_t)(32 + 32 * j + k) * DDIM + d] = __float2half_rn(Bp[j]);
        Wh[(size_t)(160 + k) * DDIM + d] = __float2half_rn(-0.5f * iD);
    }
}

// ---------------------------------------------------------------------------
// Stage B: persistent 512-thread kernel, 16 warps = (wm 0-7 rows16) x (wk 0-1).
// Double-buffered x tile; next tile LDG-staged before GEMM, STS'd mid-GEMM.
// s1 GEMM accumulates into the s2 accumulator (weights carry -0.5).
// ---------------------------------------------------------------------------
__global__ void __launch_bounds__(TPB, 1)
mfa_mma(const float* __restrict__ x, float* __restrict__ out, int N, int ntiles)
{
    extern __shared__ char smc[];
    const int tid  = threadIdx.x;
    const int lane = tid & 31;
    const int w    = tid >> 5;
    const int wm   = w & 7;         // row group (16 rows)
    const int wk   = w >> 3;        // component half (16 comps)
    const int qr   = lane >> 2;     // 0..7
    const int qc   = lane & 3;      // 0..3
    const int rin  = lane & 7;
    const int mat  = lane >> 3;     // 0..3

    const uint32_t sb = smem_u32(smc);

    // ---- load weights to smem once (persistent) ---------------------------
    for (int i = tid; i < 192 * 16; i += TPB) {
        const int r = i >> 4, s = i & 15;
        uint4 v = g_Wh[i];
        *(uint4*)(smc + SM_W + r * 256 + ((s ^ (r & 7)) << 4)) = v;
    }
    {
        float* c = (float*)(smc + SM_C);
        if (tid < 32) {
            c[tid] = g_cst[tid];
            float4 b = g_bm[tid];
            c[32 + tid] = b.x; c[64 + tid] = b.y;
            c[96 + tid] = b.z; c[128 + tid] = b.w;
        }
    }

    const float* cst = (const float*)(smc + SM_C);
    const uint32_t b_pre = sb + SM_W
        + (uint32_t)(wk * 16 + (mat >> 1) * 8 + rin) * 256u;
    const uint32_t a_off = (uint32_t)(wm * 16 + (mat & 1) * 8 + rin) * 256u;

    // staging indices: thread covers 4 uint4 slots of the 128x16 tile
    const int st_r[4] = { tid >> 4, (tid + 512) >> 4, (tid + 1024) >> 4, (tid + 1536) >> 4 };
    const int st_s    = tid & 15;
    const uint32_t st_off[4] = {
        (uint32_t)(st_r[0] * 256 + ((st_s ^ (st_r[0] & 7)) << 4)),
        (uint32_t)(st_r[1] * 256 + ((st_s ^ (st_r[1] & 7)) << 4)),
        (uint32_t)(st_r[2] * 256 + ((st_s ^ (st_r[2] & 7)) << 4)),
        (uint32_t)(st_r[3] * 256 + ((st_s ^ (st_r[3] & 7)) << 4)) };

    // ---- prologue: load first tile into buffer 0 --------------------------
    {
        const int row0 = blockIdx.x * ROWS_TILE;
#pragma unroll
        for (int j = 0; j < 4; j++) {
            int row = row0 + st_r[j];
            row = row < N ? row : N - 1;
            const float4* p = (const float4*)x + (size_t)row * 32 + st_s * 2;
            const float4 v0 = __ldg(p), v1 = __ldg(p + 1);
            uint4 hx;
            hx.x = h2pack(v0.x, v0.y); hx.y = h2pack(v0.z, v0.w);
            hx.z = h2pack(v1.x, v1.y); hx.w = h2pack(v1.z, v1.w);
            *(uint4*)(smc + SM_X0 + st_off[j]) = hx;
        }
    }
    __syncthreads();

    int buf = 0;
    for (int tile = blockIdx.x; tile < ntiles; tile += gridDim.x) {
        const int row0 = tile * ROWS_TILE;
        const uint32_t a_pre = sb + (buf ? SM_X1 : SM_X0) + a_off;
        char* nxt = smc + (buf ? SM_X0 : SM_X1);

        // ---- issue next tile's LDGs (fp32, 32 regs) -----------------------
        float4 stv[8];
        {
            const int row0n = row0 + gridDim.x * ROWS_TILE;
#pragma unroll
            for (int j = 0; j < 4; j++) {
                int row = row0n + st_r[j];
                row = row < N ? row : N - 1;
                const float4* p = (const float4*)x + (size_t)row * 32 + st_s * 2;
                stv[2 * j]     = __ldg(p);
                stv[2 * j + 1] = __ldg(p + 1);
            }
        }

        // ---- GEMM: acc[g][hi][4]; g: 0=s2(-0.5 s1 folded), 1..4=z ---------
        float acc[5][2][4];
#pragma unroll
        for (int g = 0; g < 5; g++)
#pragma unroll
            for (int hi = 0; hi < 2; hi++)
#pragma unroll
                for (int e = 0; e < 4; e++) acc[g][hi][e] = 0.f;

#pragma unroll
        for (int ch = 0; ch < 8; ch++) {
            const uint32_t xa = (((uint32_t)(ch * 2 + (mat >> 1))) ^ (uint32_t)rin) << 4;
            const uint32_t xb = (((uint32_t)(ch * 2 + (mat & 1)))  ^ (uint32_t)rin) << 4;

            uint32_t ax[4];
            ldsm4(ax, a_pre + xa);

#pragma unroll
            for (int g = 0; g < 5; g++) {
                uint32_t b[4];
                ldsm4(b, b_pre + (uint32_t)g * 8192u + xb);
                mma16816(acc[g][0], ax, b[0], b[1]);
                mma16816(acc[g][1], ax, b[2], b[3]);
            }
            {
                uint32_t aq[4];
#pragma unroll
                for (int j = 0; j < 4; j++) aq[j] = sq2(ax[j]);
                uint32_t b[4];
                ldsm4(b, b_pre + 5u * 8192u + xb);
                mma16816(acc[0][0], aq, b[0], b[1]);
                mma16816(acc[0][1], aq, b[2], b[3]);
            }

            // mid-GEMM: drain staged tile into the other buffer
            if (ch == 3) {
#pragma unroll
                for (int j = 0; j < 4; j++) {
                    const float4 v0 = stv[2 * j], v1 = stv[2 * j + 1];
                    uint4 hx;
                    hx.x = h2pack(v0.x, v0.y); hx.y = h2pack(v0.z, v0.w);
                    hx.z = h2pack(v1.x, v1.y); hx.w = h2pack(v1.z, v1.w);
                    *(uint4*)(nxt + st_off[j]) = hx;
                }
            }
        }

        // ---- partial epilogue: common max, then exp ------------------------
        float2* sP = (float2*)(smc + SM_P + (buf ? 2048 : 0));
#pragma unroll
        for (int h = 0; h < 2; h++) {
            float ll[4];
#pragma unroll
            for (int hi = 0; hi < 2; hi++) {
#pragma unroll
                for (int p = 0; p < 2; p++) {
                    const int k = wk * 16 + hi * 8 + 2 * qc + p;
                    const int e = 2 * h + p;
                    float v = cst[k] + acc[0][hi][e];
#pragma unroll
                    for (int jj = 0; jj < 4; jj++) {
                        const float z = acc[1 + jj][hi][e]
                                      - cst[32 + 32 * jj + k];
                        v = fmaf(0.5f * z, z, v);
                    }
                    ll[hi * 2 + p] = v;
                }
            }
            float mx = fmaxf(fmaxf(ll[0], ll[1]), fmaxf(ll[2], ll[3]));
#pragma unroll
            for (int off = 1; off <= 2; off <<= 1)
                mx = fmaxf(mx, __shfl_xor_sync(0xffffffffu, mx, off));
            float sum = __expf(ll[0] - mx) + __expf(ll[1] - mx)
                      + __expf(ll[2] - mx) + __expf(ll[3] - mx);
#pragma unroll
            for (int off = 1; off <= 2; off <<= 1)
                sum += __shfl_xor_sync(0xffffffffu, sum, off);

            if (qc == 0)
                sP[wk * 128 + wm * 16 + qr + 8 * h] = make_float2(mx, sum);
        }
        __syncthreads();   // covers: sP writes, next-buffer STS, cur-buffer reads

        // ---- combine the two component halves, write out ------------------
        if (tid < 128) {
            const float2 a = sP[tid];
            const float2 b = sP[128 + tid];
            const float m = fmaxf(a.x, b.x);
            const float s = a.y * __expf(a.x - m) + b.y * __expf(b.x - m);
            const int row = row0 + tid;
            if (row < N) out[row] = m + __logf(s);
        }
        buf ^= 1;
    }
}

// ---------------------------------------------------------------------------
extern "C" void kernel_launch(void* const* d_in, const int* in_sizes, int n_in,
                              void* d_out, int out_size)
{
    const float* x  = (const float*)d_in[0];
    const float* MU = (const float*)d_in[1];
    const float* A  = (const float*)d_in[2];
    const float* Dm = (const float*)d_in[3];
    const float* PI = (const float*)d_in[4];
    float* out = (float*)d_out;

    const int N = in_sizes[0] / DDIM;
    const int ntiles = (N + ROWS_TILE - 1) / ROWS_TILE;

    int nsm = 148;
    cudaDeviceGetAttribute(&nsm, cudaDevAttrMultiProcessorCount, 0);
    if (nsm <= 0) nsm = 148;
    int grid = nsm < ntiles ? nsm : ntiles;

    cudaFuncSetAttribute(mfa_mma, cudaFuncAttributeMaxDynamicSharedMemorySize,
                         SMEM_TOTAL);

    mfa_precompute<<<KCOMP, 32>>>(MU, A, Dm, PI);
    mfa_mma<<<grid, TPB, SMEM_TOTAL>>>(x, out, N, ntiles);
}

// round 10
// speedup vs baseline: 1.3216x; 1.0051x over previous
#include <cuda_runtime.h>
#include <math.h>
#include <float.h>
#include <stdint.h>
#include <cuda_fp16.h>

#define KCOMP 32
#define DDIM  128
#define LDIM  4
#define TPB   512
#define ROWS_TILE 256

// smem byte offsets (~185KB, 1 CTA/SM, 512 threads)
#define SM_W   0         // weights: 192 rows x 256B (fp16) = 49152
#define SM_X0  49152     // x tile buffer 0: 256 x 256B = 65536
#define SM_X1  114688    // x tile buffer 1
#define SM_C   180224    // cst[32] + bm[4][32] floats = 640
#define SM_P   180864    // sP: 2 x 512 float2 = 8192
#define SMEM_TOTAL 189056

// ---- device globals -------------------------------------------------------
__device__ uint4  g_Wh[192 * 16];      // fp16 weights, row n: 128 halves
__device__ float  g_cst[KCOMP];
__device__ float4 g_bm[KCOMP];

// ---- helpers --------------------------------------------------------------
__device__ __forceinline__ uint32_t h2pack(float a, float b) {
    __half2 h = __floats2half2_rn(a, b);
    return *(uint32_t*)&h;
}
__device__ __forceinline__ uint32_t smem_u32(const void* p) {
    uint32_t a;
    asm("{ .reg .u64 t; cvta.to.shared.u64 t, %1; cvt.u32.u64 %0, t; }" : "=r"(a) : "l"(p));
    return a;
}
__device__ __forceinline__ void mma16816(float c[4], const uint32_t a[4],
                                         uint32_t b0, uint32_t b1) {
    asm volatile(
        "mma.sync.aligned.m16n8k16.row.col.f32.f16.f16.f32 "
        "{%0,%1,%2,%3}, {%4,%5,%6,%7}, {%8,%9}, {%0,%1,%2,%3};"
        : "+f"(c[0]), "+f"(c[1]), "+f"(c[2]), "+f"(c[3])
        : "r"(a[0]), "r"(a[1]), "r"(a[2]), "r"(a[3]), "r"(b0), "r"(b1));
}
__device__ __forceinline__ void ldsm4(uint32_t r[4], uint32_t addr) {
    asm volatile("ldmatrix.sync.aligned.m8n8.x4.shared.b16 {%0,%1,%2,%3}, [%4];"
        : "=r"(r[0]), "=r"(r[1]), "=r"(r[2]), "=r"(r[3]) : "r"(addr));
}
__device__ __forceinline__ uint32_t sq2(uint32_t a) {
    __half2 h = *(__half2*)&a;
    h = __hmul2(h, h);
    return *(uint32_t*)&h;
}

// ---------------------------------------------------------------------------
// Stage A: per-component precompute. 32 blocks x 1 warp; fp32 throughout.
// s1 weight rows carry -0.5*iD (folded into the s2 accumulator).
// ---------------------------------------------------------------------------
__global__ void mfa_precompute(const float* __restrict__ MU,
                               const float* __restrict__ A,
                               const float* __restrict__ Dm,
                               const float* __restrict__ PI)
{
    const int k    = blockIdx.x;
    const int lane = threadIdx.x;

    float s[22];
#pragma unroll
    for (int j = 0; j < 22; j++) s[j] = 0.f;

#pragma unroll
    for (int i = 0; i < 4; i++) {
        const int d = lane + 32 * i;
        const float Dv = Dm[k * DDIM + d];
        const float iD = 1.0f / (Dv * Dv);
        const float mu = MU[k * DDIM + d];
        float a[LDIM], B[LDIM];
#pragma unroll
        for (int l = 0; l < LDIM; l++) {
            a[l] = A[(k * DDIM + d) * LDIM + l];
            B[l] = iD * a[l];
        }
        int idx = 0;
#pragma unroll
        for (int l = 0; l < LDIM; l++)
#pragma unroll
            for (int m = 0; m < LDIM; m++)
                s[idx++] += a[l] * B[m];
#pragma unroll
        for (int m = 0; m < LDIM; m++)
            s[idx++] += mu * B[m];
        s[20] += iD * mu * mu;
        s[21] += 2.0f * logf(Dv);
    }

#pragma unroll
    for (int j = 0; j < 22; j++)
#pragma unroll
        for (int o = 16; o; o >>= 1)
            s[j] += __shfl_xor_sync(0xffffffffu, s[j], o);

    float Lm[LDIM][LDIM], bmu[LDIM];
#pragma unroll
    for (int l = 0; l < LDIM; l++)
#pragma unroll
        for (int m = 0; m < LDIM; m++)
            Lm[l][m] = s[l * LDIM + m] + (l == m ? 1.0f : 0.0f);
#pragma unroll
    for (int m = 0; m < LDIM; m++) bmu[m] = s[16 + m];
    const float tc  = s[20];
    const float sld = s[21];

    float G[LDIM][LDIM] = {};
#pragma unroll
    for (int i = 0; i < LDIM; i++) {
#pragma unroll
        for (int j = 0; j <= i; j++) {
            float v = Lm[i][j];
#pragma unroll
            for (int p = 0; p < LDIM; p++)
                if (p < j) v -= G[i][p] * G[j][p];
            if (i == j) G[i][i] = sqrtf(v);
            else        G[i][j] = v / G[j][j];
        }
    }
    float logdetL = 0.f;
#pragma unroll
    for (int i = 0; i < LDIM; i++) logdetL += 2.0f * logf(G[i][i]);

    float U[LDIM][LDIM] = {};
#pragma unroll
    for (int j = 0; j < LDIM; j++) {
        U[j][j] = 1.0f / G[j][j];
#pragma unroll
        for (int i = 0; i < LDIM; i++) {
            if (i > j) {
                float v = 0.f;
#pragma unroll
                for (int p = 0; p < LDIM; p++)
                    if (p >= j && p < i) v += G[i][p] * U[p][j];
                U[i][j] = -v / G[i][i];
            }
        }
    }

    if (lane == 0) {
        const float LOG2PI = 1.8378770664093454835606594728112f;
        g_cst[k] = PI[k] - 0.5f * ((float)DDIM * LOG2PI + logdetL + sld + tc);
        float bp[LDIM];
#pragma unroll
        for (int l = 0; l < LDIM; l++) {
            float v = 0.f;
#pragma unroll
            for (int m = 0; m <= l; m++) v += U[l][m] * bmu[m];
            bp[l] = v;
        }
        g_bm[k] = make_float4(bp[0], bp[1], bp[2], bp[3]);
    }

    __half* Wh = (__half*)g_Wh;
#pragma unroll
    for (int i = 0; i < 4; i++) {
        const int d = lane + 32 * i;
        const float Dv = Dm[k * DDIM + d];
        const float iD = 1.0f / (Dv * Dv);
        const float mu = MU[k * DDIM + d];
        float B[LDIM];
#pragma unroll
        for (int l = 0; l < LDIM; l++)
            B[l] = iD * A[(k * DDIM + d) * LDIM + l];
        float Bp[LDIM];
#pragma unroll
        for (int l = 0; l < LDIM; l++) {
            float v = 0.f;
#pragma unroll
            for (int m = 0; m <= l; m++) v += U[l][m] * B[m];
            Bp[l] = v;
        }
        Wh[(size_t)k * DDIM + d] = __float2half_rn(iD * mu);
#pragma unroll
        for (int j = 0; j < LDIM; j++)
            Wh[(size_t)(32 + 32 * j + k) * DDIM + d] = __float2half_rn(Bp[j]);
        Wh[(size_t)(160 + k) * DDIM + d] = __float2half_rn(-0.5f * iD);
    }
}

// ---------------------------------------------------------------------------
// Stage B: persistent 512-thread kernel, 256-row tiles.
// 16 warps = (wm 0-7, 32 rows each) x (wk 0-1, 16 comps).
// Double-buffered x tile; next tile LDG-staged in 2 batches, STS'd mid-GEMM.
// ---------------------------------------------------------------------------
__global__ void __launch_bounds__(TPB, 1)
mfa_mma(const float* __restrict__ x, float* __restrict__ out, int N, int ntiles)
{
    extern __shared__ char smc[];
    const int tid  = threadIdx.x;
    const int lane = tid & 31;
    const int w    = tid >> 5;
    const int wm   = w & 7;         // row group (32 rows)
    const int wk   = w >> 3;        // component half (16 comps)
    const int qr   = lane >> 2;     // 0..7
    const int qc   = lane & 3;      // 0..3
    const int rin  = lane & 7;
    const int mat  = lane >> 3;     // 0..3

    const uint32_t sb = smem_u32(smc);

    // ---- load weights to smem once (persistent) ---------------------------
    for (int i = tid; i < 192 * 16; i += TPB) {
        const int r = i >> 4, s = i & 15;
        uint4 v = g_Wh[i];
        *(uint4*)(smc + SM_W + r * 256 + ((s ^ (r & 7)) << 4)) = v;
    }
    {
        float* c = (float*)(smc + SM_C);
        if (tid < 32) {
            c[tid] = g_cst[tid];
            float4 b = g_bm[tid];
            c[32 + tid] = b.x; c[64 + tid] = b.y;
            c[96 + tid] = b.z; c[128 + tid] = b.w;
        }
    }

    const float* cst = (const float*)(smc + SM_C);
    const uint32_t b_pre = sb + SM_W
        + (uint32_t)(wk * 16 + (mat >> 1) * 8 + rin) * 256u;
    uint32_t a_off[2];
#pragma unroll
    for (int mt = 0; mt < 2; mt++)
        a_off[mt] = (uint32_t)(wm * 32 + mt * 16 + (mat & 1) * 8 + rin) * 256u;

    // staging: 256x16 = 4096 uint4 slots; 8 per thread, in 2 batches of 4
    int st_r[8];
    uint32_t st_off[8];
#pragma unroll
    for (int j = 0; j < 8; j++) {
        const int slot = tid + j * TPB;
        st_r[j] = slot >> 4;
        const int ss = slot & 15;
        st_off[j] = (uint32_t)(st_r[j] * 256 + ((ss ^ (st_r[j] & 7)) << 4));
    }
    const int st_s = tid & 15;

    // ---- prologue: load first tile into buffer 0 --------------------------
    {
        const int row0 = blockIdx.x * ROWS_TILE;
#pragma unroll
        for (int j = 0; j < 8; j++) {
            int row = row0 + st_r[j];
            row = row < N ? row : N - 1;
            const float4* p = (const float4*)x + (size_t)row * 32 + st_s * 2;
            const float4 v0 = __ldg(p), v1 = __ldg(p + 1);
            uint4 hx;
            hx.x = h2pack(v0.x, v0.y); hx.y = h2pack(v0.z, v0.w);
            hx.z = h2pack(v1.x, v1.y); hx.w = h2pack(v1.z, v1.w);
            *(uint4*)(smc + SM_X0 + st_off[j]) = hx;
        }
    }
    __syncthreads();

    int buf = 0;
    for (int tile = blockIdx.x; tile < ntiles; tile += gridDim.x) {
        const int row0 = tile * ROWS_TILE;
        const uint32_t xb_base = sb + (buf ? SM_X1 : SM_X0);
        char* nxt = smc + (buf ? SM_X0 : SM_X1);
        const int row0n = row0 + gridDim.x * ROWS_TILE;

        // ---- batch 0 LDGs for next tile (8 float4 = 32 regs) --------------
        float4 stv[8];
#pragma unroll
        for (int j = 0; j < 4; j++) {
            int row = row0n + st_r[j];
            row = row < N ? row : N - 1;
            const float4* p = (const float4*)x + (size_t)row * 32 + st_s * 2;
            stv[2 * j]     = __ldg(p);
            stv[2 * j + 1] = __ldg(p + 1);
        }

        // ---- GEMM: acc[mt][g][hi][4]; g: 0=s2(+s1 folded), 1..4=z ---------
        float acc[2][5][2][4];
#pragma unroll
        for (int mt = 0; mt < 2; mt++)
#pragma unroll
            for (int g = 0; g < 5; g++)
#pragma unroll
                for (int hi = 0; hi < 2; hi++)
#pragma unroll
                    for (int e = 0; e < 4; e++) acc[mt][g][hi][e] = 0.f;

#pragma unroll
        for (int ch = 0; ch < 8; ch++) {
            const uint32_t xa = (((uint32_t)(ch * 2 + (mat >> 1))) ^ (uint32_t)rin) << 4;
            const uint32_t xb = (((uint32_t)(ch * 2 + (mat & 1)))  ^ (uint32_t)rin) << 4;

            uint32_t ax[2][4];
            ldsm4(ax[0], xb_base + a_off[0] + xa);
            ldsm4(ax[1], xb_base + a_off[1] + xa);

#pragma unroll
            for (int g = 0; g < 5; g++) {
                uint32_t b[4];
                ldsm4(b, b_pre + (uint32_t)g * 8192u + xb);
                mma16816(acc[0][g][0], ax[0], b[0], b[1]);
                mma16816(acc[0][g][1], ax[0], b[2], b[3]);
                mma16816(acc[1][g][0], ax[1], b[0], b[1]);
                mma16816(acc[1][g][1], ax[1], b[2], b[3]);
            }
            {
                uint32_t aq[2][4];
#pragma unroll
                for (int j = 0; j < 4; j++) {
                    aq[0][j] = sq2(ax[0][j]);
                    aq[1][j] = sq2(ax[1][j]);
                }
                uint32_t b[4];
                ldsm4(b, b_pre + 5u * 8192u + xb);
                mma16816(acc[0][0][0], aq[0], b[0], b[1]);
                mma16816(acc[0][0][1], aq[0], b[2], b[3]);
                mma16816(acc[1][0][0], aq[1], b[0], b[1]);
                mma16816(acc[1][0][1], aq[1], b[2], b[3]);
            }

            // drain batch 0, issue batch 1
            if (ch == 2) {
#pragma unroll
                for (int j = 0; j < 4; j++) {
                    const float4 v0 = stv[2 * j], v1 = stv[2 * j + 1];
                    uint4 hx;
                    hx.x = h2pack(v0.x, v0.y); hx.y = h2pack(v0.z, v0.w);
                    hx.z = h2pack(v1.x, v1.y); hx.w = h2pack(v1.z, v1.w);
                    *(uint4*)(nxt + st_off[j]) = hx;
                }
#pragma unroll
                for (int j = 0; j < 4; j++) {
                    int row = row0n + st_r[4 + j];
                    row = row < N ? row : N - 1;
                    const float4* p = (const float4*)x + (size_t)row * 32 + st_s * 2;
                    stv[2 * j]     = __ldg(p);
                    stv[2 * j + 1] = __ldg(p + 1);
                }
            }
            // drain batch 1
            if (ch == 5) {
#pragma unroll
                for (int j = 0; j < 4; j++) {
                    const float4 v0 = stv[2 * j], v1 = stv[2 * j + 1];
                    uint4 hx;
                    hx.x = h2pack(v0.x, v0.y); hx.y = h2pack(v0.z, v0.w);
                    hx.z = h2pack(v1.x, v1.y); hx.w = h2pack(v1.z, v1.w);
                    *(uint4*)(nxt + st_off[4 + j]) = hx;
                }
            }
        }

        // ---- partial epilogue: common max, then exp ------------------------
        float2* sP = (float2*)(smc + SM_P + (buf ? 4096 : 0));
#pragma unroll
        for (int mt = 0; mt < 2; mt++) {
#pragma unroll
            for (int h = 0; h < 2; h++) {
                float ll[4];
#pragma unroll
                for (int hi = 0; hi < 2; hi++) {
#pragma unroll
                    for (int p = 0; p < 2; p++) {
                        const int k = wk * 16 + hi * 8 + 2 * qc + p;
                        const int e = 2 * h + p;
                        float v = cst[k] + acc[mt][0][hi][e];
#pragma unroll
                        for (int jj = 0; jj < 4; jj++) {
                            const float z = acc[mt][1 + jj][hi][e]
                                          - cst[32 + 32 * jj + k];
                            v = fmaf(0.5f * z, z, v);
                        }
                        ll[hi * 2 + p] = v;
                    }
                }
                float mx = fmaxf(fmaxf(ll[0], ll[1]), fmaxf(ll[2], ll[3]));
#pragma unroll
                for (int off = 1; off <= 2; off <<= 1)
                    mx = fmaxf(mx, __shfl_xor_sync(0xffffffffu, mx, off));
                float sum = __expf(ll[0] - mx) + __expf(ll[1] - mx)
                          + __expf(ll[2] - mx) + __expf(ll[3] - mx);
#pragma unroll
                for (int off = 1; off <= 2; off <<= 1)
                    sum += __shfl_xor_sync(0xffffffffu, sum, off);

                if (qc == 0)
                    sP[wk * 256 + wm * 32 + mt * 16 + qr + 8 * h]
                        = make_float2(mx, sum);
            }
        }
        __syncthreads();   // covers: sP writes, next-buffer STS, cur-buffer reads

        // ---- combine the two component halves, write out ------------------
        if (tid < 256) {
            const float2 a = sP[tid];
            const float2 b = sP[256 + tid];
            const float m = fmaxf(a.x, b.x);
            const float s = a.y * __expf(a.x - m) + b.y * __expf(b.x - m);
            const int row = row0 + tid;
            if (row < N) out[row] = m + __logf(s);
        }
        buf ^= 1;
    }
}

// ---------------------------------------------------------------------------
extern "C" void kernel_launch(void* const* d_in, const int* in_sizes, int n_in,
                              void* d_out, int out_size)
{
    const float* x  = (const float*)d_in[0];
    const float* MU = (const float*)d_in[1];
    const float* A  = (const float*)d_in[2];
    const float* Dm = (const float*)d_in[3];
    const float* PI = (const float*)d_in[4];
    float* out = (float*)d_out;

    const int N = in_sizes[0] / DDIM;
    const int ntiles = (N + ROWS_TILE - 1) / ROWS_TILE;

    int nsm = 148;
    cudaDeviceGetAttribute(&nsm, cudaDevAttrMultiProcessorCount, 0);
    if (nsm <= 0) nsm = 148;
    int grid = nsm < ntiles ? nsm : ntiles;

    cudaFuncSetAttribute(mfa_mma, cudaFuncAttributeMaxDynamicSharedMemorySize,
                         SMEM_TOTAL);

    mfa_precompute<<<KCOMP, 32>>>(MU, A, Dm, PI);
    mfa_mma<<<grid, TPB, SMEM_TOTAL>>>(x, out, N, ntiles);
}

// round 11
// speedup vs baseline: 1.4347x; 1.0856x over previous
#include <cuda_runtime.h>
#include <math.h>
#include <float.h>
#include <stdint.h>
#include <cuda_fp16.h>

#define KCOMP 32
#define DDIM  128
#define LDIM  4
#define TPB   512
#define ROWS_TILE 256

// smem byte offsets (~185KB, 1 CTA/SM, 512 threads)
#define SM_W   0         // weights: 192 rows x 256B (fp16) = 49152
#define SM_X0  49152     // x tile buffer 0: 256 x 256B = 65536
#define SM_X1  114688    // x tile buffer 1
#define SM_C   180224    // cst[32] + bm[4][32] floats = 640
#define SM_P   180864    // sP: 2 x 512 float2 = 8192
#define SMEM_TOTAL 189056

// ---- device globals -------------------------------------------------------
__device__ uint4  g_Wh[192 * 16];      // fp16 weights, row n: 128 halves
__device__ float  g_cst[KCOMP];
__device__ float4 g_bm[KCOMP];

// ---- helpers --------------------------------------------------------------
__device__ __forceinline__ uint32_t h2pack(float a, float b) {
    __half2 h = __floats2half2_rn(a, b);
    return *(uint32_t*)&h;
}
__device__ __forceinline__ uint32_t smem_u32(const void* p) {
    uint32_t a;
    asm("{ .reg .u64 t; cvta.to.shared.u64 t, %1; cvt.u32.u64 %0, t; }" : "=r"(a) : "l"(p));
    return a;
}
// fp32-accumulate MMA (s2/s1 path)
__device__ __forceinline__ void mma16816(float c[4], const uint32_t a[4],
                                         uint32_t b0, uint32_t b1) {
    asm volatile(
        "mma.sync.aligned.m16n8k16.row.col.f32.f16.f16.f32 "
        "{%0,%1,%2,%3}, {%4,%5,%6,%7}, {%8,%9}, {%0,%1,%2,%3};"
        : "+f"(c[0]), "+f"(c[1]), "+f"(c[2]), "+f"(c[3])
        : "r"(a[0]), "r"(a[1]), "r"(a[2]), "r"(a[3]), "r"(b0), "r"(b1));
}
// fp16-accumulate MMA (z path): d0={c0,c1}, d1={c2,c3}
__device__ __forceinline__ void mma16816h(uint32_t c[2], const uint32_t a[4],
                                          uint32_t b0, uint32_t b1) {
    asm volatile(
        "mma.sync.aligned.m16n8k16.row.col.f16.f16.f16.f16 "
        "{%0,%1}, {%2,%3,%4,%5}, {%6,%7}, {%0,%1};"
        : "+r"(c[0]), "+r"(c[1])
        : "r"(a[0]), "r"(a[1]), "r"(a[2]), "r"(a[3]), "r"(b0), "r"(b1));
}
__device__ __forceinline__ void ldsm4(uint32_t r[4], uint32_t addr) {
    asm volatile("ldmatrix.sync.aligned.m8n8.x4.shared.b16 {%0,%1,%2,%3}, [%4];"
        : "=r"(r[0]), "=r"(r[1]), "=r"(r[2]), "=r"(r[3]) : "r"(addr));
}
__device__ __forceinline__ uint32_t sq2(uint32_t a) {
    __half2 h = *(__half2*)&a;
    h = __hmul2(h, h);
    return *(uint32_t*)&h;
}

// ---------------------------------------------------------------------------
// Stage A: per-component precompute. 32 blocks x 1 warp; fp32 throughout.
// s1 weight rows carry -0.5*iD (folded into the s2 accumulator).
// ---------------------------------------------------------------------------
__global__ void mfa_precompute(const float* __restrict__ MU,
                               const float* __restrict__ A,
                               const float* __restrict__ Dm,
                               const float* __restrict__ PI)
{
    const int k    = blockIdx.x;
    const int lane = threadIdx.x;

    float s[22];
#pragma unroll
    for (int j = 0; j < 22; j++) s[j] = 0.f;

#pragma unroll
    for (int i = 0; i < 4; i++) {
        const int d = lane + 32 * i;
        const float Dv = Dm[k * DDIM + d];
        const float iD = 1.0f / (Dv * Dv);
        const float mu = MU[k * DDIM + d];
        float a[LDIM], B[LDIM];
#pragma unroll
        for (int l = 0; l < LDIM; l++) {
            a[l] = A[(k * DDIM + d) * LDIM + l];
            B[l] = iD * a[l];
        }
        int idx = 0;
#pragma unroll
        for (int l = 0; l < LDIM; l++)
#pragma unroll
            for (int m = 0; m < LDIM; m++)
                s[idx++] += a[l] * B[m];
#pragma unroll
        for (int m = 0; m < LDIM; m++)
            s[idx++] += mu * B[m];
        s[20] += iD * mu * mu;
        s[21] += 2.0f * logf(Dv);
    }

#pragma unroll
    for (int j = 0; j < 22; j++)
#pragma unroll
        for (int o = 16; o; o >>= 1)
            s[j] += __shfl_xor_sync(0xffffffffu, s[j], o);

    float Lm[LDIM][LDIM], bmu[LDIM];
#pragma unroll
    for (int l = 0; l < LDIM; l++)
#pragma unroll
        for (int m = 0; m < LDIM; m++)
            Lm[l][m] = s[l * LDIM + m] + (l == m ? 1.0f : 0.0f);
#pragma unroll
    for (int m = 0; m < LDIM; m++) bmu[m] = s[16 + m];
    const float tc  = s[20];
    const float sld = s[21];

    float G[LDIM][LDIM] = {};
#pragma unroll
    for (int i = 0; i < LDIM; i++) {
#pragma unroll
        for (int j = 0; j <= i; j++) {
            float v = Lm[i][j];
#pragma unroll
            for (int p = 0; p < LDIM; p++)
                if (p < j) v -= G[i][p] * G[j][p];
            if (i == j) G[i][i] = sqrtf(v);
            else        G[i][j] = v / G[j][j];
        }
    }
    float logdetL = 0.f;
#pragma unroll
    for (int i = 0; i < LDIM; i++) logdetL += 2.0f * logf(G[i][i]);

    float U[LDIM][LDIM] = {};
#pragma unroll
    for (int j = 0; j < LDIM; j++) {
        U[j][j] = 1.0f / G[j][j];
#pragma unroll
        for (int i = 0; i < LDIM; i++) {
            if (i > j) {
                float v = 0.f;
#pragma unroll
                for (int p = 0; p < LDIM; p++)
                    if (p >= j && p < i) v += G[i][p] * U[p][j];
                U[i][j] = -v / G[i][i];
            }
        }
    }

    if (lane == 0) {
        const float LOG2PI = 1.8378770664093454835606594728112f;
        g_cst[k] = PI[k] - 0.5f * ((float)DDIM * LOG2PI + logdetL + sld + tc);
        float bp[LDIM];
#pragma unroll
        for (int l = 0; l < LDIM; l++) {
            float v = 0.f;
#pragma unroll
            for (int m = 0; m <= l; m++) v += U[l][m] * bmu[m];
            bp[l] = v;
        }
        g_bm[k] = make_float4(bp[0], bp[1], bp[2], bp[3]);
    }

    __half* Wh = (__half*)g_Wh;
#pragma unroll
    for (int i = 0; i < 4; i++) {
        const int d = lane + 32 * i;
        const float Dv = Dm[k * DDIM + d];
        const float iD = 1.0f / (Dv * Dv);
        const float mu = MU[k * DDIM + d];
        float B[LDIM];
#pragma unroll
        for (int l = 0; l < LDIM; l++)
            B[l] = iD * A[(k * DDIM + d) * LDIM + l];
        float Bp[LDIM];
#pragma unroll
        for (int l = 0; l < LDIM; l++) {
            float v = 0.f;
#pragma unroll
            for (int m = 0; m <= l; m++) v += U[l][m] * B[m];
            Bp[l] = v;
        }
        Wh[(size_t)k * DDIM + d] = __float2half_rn(iD * mu);
#pragma unroll
        for (int j = 0; j < LDIM; j++)
            Wh[(size_t)(32 + 32 * j + k) * DDIM + d] = __float2half_rn(Bp[j]);
        Wh[(size_t)(160 + k) * DDIM + d] = __float2half_rn(-0.5f * iD);
    }
}

// ---------------------------------------------------------------------------
// Stage B: persistent 512-thread kernel, 256-row tiles.
// 16 warps = (wm 0-7, 32 rows each) x (wk 0-1, 16 comps).
// z-group accumulators in fp16 (2 regs/group) to free registers for
// ptxas software pipelining; s2/s1 accumulator stays fp32.
// ---------------------------------------------------------------------------
__global__ void __launch_bounds__(TPB, 1)
mfa_mma(const float* __restrict__ x, float* __restrict__ out, int N, int ntiles)
{
    extern __shared__ char smc[];
    const int tid  = threadIdx.x;
    const int lane = tid & 31;
    const int w    = tid >> 5;
    const int wm   = w & 7;         // row group (32 rows)
    const int wk   = w >> 3;        // component half (16 comps)
    const int qr   = lane >> 2;     // 0..7
    const int qc   = lane & 3;      // 0..3
    const int rin  = lane & 7;
    const int mat  = lane >> 3;     // 0..3

    const uint32_t sb = smem_u32(smc);

    // ---- load weights to smem once (persistent) ---------------------------
    for (int i = tid; i < 192 * 16; i += TPB) {
        const int r = i >> 4, s = i & 15;
        uint4 v = g_Wh[i];
        *(uint4*)(smc + SM_W + r * 256 + ((s ^ (r & 7)) << 4)) = v;
    }
    {
        float* c = (float*)(smc + SM_C);
        if (tid < 32) {
            c[tid] = g_cst[tid];
            float4 b = g_bm[tid];
            c[32 + tid] = b.x; c[64 + tid] = b.y;
            c[96 + tid] = b.z; c[128 + tid] = b.w;
        }
    }

    const float* cst = (const float*)(smc + SM_C);
    const uint32_t b_pre = sb + SM_W
        + (uint32_t)(wk * 16 + (mat >> 1) * 8 + rin) * 256u;
    uint32_t a_off[2];
#pragma unroll
    for (int mt = 0; mt < 2; mt++)
        a_off[mt] = (uint32_t)(wm * 32 + mt * 16 + (mat & 1) * 8 + rin) * 256u;

    // staging: 256x16 = 4096 uint4 slots; 8 per thread, in 2 batches of 4
    int st_r[8];
    uint32_t st_off[8];
#pragma unroll
    for (int j = 0; j < 8; j++) {
        const int slot = tid + j * TPB;
        st_r[j] = slot >> 4;
        const int ss = slot & 15;
        st_off[j] = (uint32_t)(st_r[j] * 256 + ((ss ^ (st_r[j] & 7)) << 4));
    }
    const int st_s = tid & 15;

    // ---- prologue: load first tile into buffer 0 --------------------------
    {
        const int row0 = blockIdx.x * ROWS_TILE;
#pragma unroll
        for (int j = 0; j < 8; j++) {
            int row = row0 + st_r[j];
            row = row < N ? row : N - 1;
            const float4* p = (const float4*)x + (size_t)row * 32 + st_s * 2;
            const float4 v0 = __ldg(p), v1 = __ldg(p + 1);
            uint4 hx;
            hx.x = h2pack(v0.x, v0.y); hx.y = h2pack(v0.z, v0.w);
            hx.z = h2pack(v1.x, v1.y); hx.w = h2pack(v1.z, v1.w);
            *(uint4*)(smc + SM_X0 + st_off[j]) = hx;
        }
    }
    __syncthreads();

    int buf = 0;
    for (int tile = blockIdx.x; tile < ntiles; tile += gridDim.x) {
        const int row0 = tile * ROWS_TILE;
        const uint32_t xb_base = sb + (buf ? SM_X1 : SM_X0);
        char* nxt = smc + (buf ? SM_X0 : SM_X1);
        const int row0n = row0 + gridDim.x * ROWS_TILE;

        // ---- batch 0 LDGs for next tile (8 float4 = 32 regs) --------------
        float4 stv[8];
#pragma unroll
        for (int j = 0; j < 4; j++) {
            int row = row0n + st_r[j];
            row = row < N ? row : N - 1;
            const float4* p = (const float4*)x + (size_t)row * 32 + st_s * 2;
            stv[2 * j]     = __ldg(p);
            stv[2 * j + 1] = __ldg(p + 1);
        }

        // ---- GEMM: accS fp32 (s2 + folded s1); accZ fp16 (z groups) -------
        float    accS[2][2][4];
        uint32_t accZ[2][4][2][2];
#pragma unroll
        for (int mt = 0; mt < 2; mt++) {
#pragma unroll
            for (int hi = 0; hi < 2; hi++)
#pragma unroll
                for (int e = 0; e < 4; e++) accS[mt][hi][e] = 0.f;
#pragma unroll
            for (int jj = 0; jj < 4; jj++)
#pragma unroll
                for (int hi = 0; hi < 2; hi++) {
                    accZ[mt][jj][hi][0] = 0u;
                    accZ[mt][jj][hi][1] = 0u;
                }
        }

#pragma unroll
        for (int ch = 0; ch < 8; ch++) {
            const uint32_t xa = (((uint32_t)(ch * 2 + (mat >> 1))) ^ (uint32_t)rin) << 4;
            const uint32_t xb = (((uint32_t)(ch * 2 + (mat & 1)))  ^ (uint32_t)rin) << 4;

            uint32_t ax[2][4];
            ldsm4(ax[0], xb_base + a_off[0] + xa);
            ldsm4(ax[1], xb_base + a_off[1] + xa);

            // g0: s2 (fp32 acc)
            {
                uint32_t b[4];
                ldsm4(b, b_pre + xb);
                mma16816(accS[0][0], ax[0], b[0], b[1]);
                mma16816(accS[0][1], ax[0], b[2], b[3]);
                mma16816(accS[1][0], ax[1], b[0], b[1]);
                mma16816(accS[1][1], ax[1], b[2], b[3]);
            }
            // z groups (fp16 acc)
#pragma unroll
            for (int jj = 0; jj < 4; jj++) {
                uint32_t b[4];
                ldsm4(b, b_pre + (uint32_t)(1 + jj) * 8192u + xb);
                mma16816h(accZ[0][jj][0], ax[0], b[0], b[1]);
                mma16816h(accZ[0][jj][1], ax[0], b[2], b[3]);
                mma16816h(accZ[1][jj][0], ax[1], b[0], b[1]);
                mma16816h(accZ[1][jj][1], ax[1], b[2], b[3]);
            }
            // s1 folded (-0.5*iD weights), fp32 acc into accS
            {
                uint32_t aq[2][4];
#pragma unroll
                for (int j = 0; j < 4; j++) {
                    aq[0][j] = sq2(ax[0][j]);
                    aq[1][j] = sq2(ax[1][j]);
                }
                uint32_t b[4];
                ldsm4(b, b_pre + 5u * 8192u + xb);
                mma16816(accS[0][0], aq[0], b[0], b[1]);
                mma16816(accS[0][1], aq[0], b[2], b[3]);
                mma16816(accS[1][0], aq[1], b[0], b[1]);
                mma16816(accS[1][1], aq[1], b[2], b[3]);
            }

            // drain batch 0, issue batch 1
            if (ch == 2) {
#pragma unroll
                for (int j = 0; j < 4; j++) {
                    const float4 v0 = stv[2 * j], v1 = stv[2 * j + 1];
                    uint4 hx;
                    hx.x = h2pack(v0.x, v0.y); hx.y = h2pack(v0.z, v0.w);
                    hx.z = h2pack(v1.x, v1.y); hx.w = h2pack(v1.z, v1.w);
                    *(uint4*)(nxt + st_off[j]) = hx;
                }
#pragma unroll
                for (int j = 0; j < 4; j++) {
                    int row = row0n + st_r[4 + j];
                    row = row < N ? row : N - 1;
                    const float4* p = (const float4*)x + (size_t)row * 32 + st_s * 2;
                    stv[2 * j]     = __ldg(p);
                    stv[2 * j + 1] = __ldg(p + 1);
                }
            }
            // drain batch 1
            if (ch == 5) {
#pragma unroll
                for (int j = 0; j < 4; j++) {
                    const float4 v0 = stv[2 * j], v1 = stv[2 * j + 1];
                    uint4 hx;
                    hx.x = h2pack(v0.x, v0.y); hx.y = h2pack(v0.z, v0.w);
                    hx.z = h2pack(v1.x, v1.y); hx.w = h2pack(v1.z, v1.w);
                    *(uint4*)(nxt + st_off[4 + j]) = hx;
                }
            }
        }

        // ---- partial epilogue: common max, then exp ------------------------
        float2* sP = (float2*)(smc + SM_P + (buf ? 4096 : 0));
#pragma unroll
        for (int mt = 0; mt < 2; mt++) {
#pragma unroll
            for (int h = 0; h < 2; h++) {
                float ll[4];
#pragma unroll
                for (int hi = 0; hi < 2; hi++) {
#pragma unroll
                    for (int p = 0; p < 2; p++) {
                        const int k = wk * 16 + hi * 8 + 2 * qc + p;
                        const int e = 2 * h + p;
                        float v = cst[k] + accS[mt][hi][e];
#pragma unroll
                        for (int jj = 0; jj < 4; jj++) {
                            const __half2 hz = *(const __half2*)&accZ[mt][jj][hi][h];
                            const float2 fz = __half22float2(hz);
                            const float z = (p ? fz.y : fz.x)
                                          - cst[32 + 32 * jj + k];
                            v = fmaf(0.5f * z, z, v);
                        }
                        ll[hi * 2 + p] = v;
                    }
                }
                float mx = fmaxf(fmaxf(ll[0], ll[1]), fmaxf(ll[2], ll[3]));
#pragma unroll
                for (int off = 1; off <= 2; off <<= 1)
                    mx = fmaxf(mx, __shfl_xor_sync(0xffffffffu, mx, off));
                float sum = __expf(ll[0] - mx) + __expf(ll[1] - mx)
                          + __expf(ll[2] - mx) + __expf(ll[3] - mx);
#pragma unroll
                for (int off = 1; off <= 2; off <<= 1)
                    sum += __shfl_xor_sync(0xffffffffu, sum, off);

                if (qc == 0)
                    sP[wk * 256 + wm * 32 + mt * 16 + qr + 8 * h]
                        = make_float2(mx, sum);
            }
        }
        __syncthreads();   // covers: sP writes, next-buffer STS, cur-buffer reads

        // ---- combine the two component halves, write out ------------------
        if (tid < 256) {
            const float2 a = sP[tid];
            const float2 b = sP[256 + tid];
            const float m = fmaxf(a.x, b.x);
            const float s = a.y * __expf(a.x - m) + b.y * __expf(b.x - m);
            const int row = row0 + tid;
            if (row < N) out[row] = m + __logf(s);
        }
        buf ^= 1;
    }
}

// ---------------------------------------------------------------------------
extern "C" void kernel_launch(void* const* d_in, const int* in_sizes, int n_in,
                              void* d_out, int out_size)
{
    const float* x  = (const float*)d_in[0];
    const float* MU = (const float*)d_in[1];
    const float* A  = (const float*)d_in[2];
    const float* Dm = (const float*)d_in[3];
    const float* PI = (const float*)d_in[4];
    float* out = (float*)d_out;

    const int N = in_sizes[0] / DDIM;
    const int ntiles = (N + ROWS_TILE - 1) / ROWS_TILE;

    int nsm = 148;
    cudaDeviceGetAttribute(&nsm, cudaDevAttrMultiProcessorCount, 0);
    if (nsm <= 0) nsm = 148;
    int grid = nsm < ntiles ? nsm : ntiles;

    cudaFuncSetAttribute(mfa_mma, cudaFuncAttributeMaxDynamicSharedMemorySize,
                         SMEM_TOTAL);

    mfa_precompute<<<KCOMP, 32>>>(MU, A, Dm, PI);
    mfa_mma<<<grid, TPB, SMEM_TOTAL>>>(x, out, N, ntiles);
}

// round 12
// speedup vs baseline: 1.6105x; 1.1225x over previous
#include <cuda_runtime.h>
#include <math.h>
#include <float.h>
#include <stdint.h>
#include <cuda_fp16.h>

#define KCOMP 32
#define DDIM  128
#define LDIM  4
#define TPB   512
#define ROWS_TILE 256

// smem byte offsets (~185KB, 1 CTA/SM, 512 threads)
#define SM_W   0         // weights: 192 rows x 256B (fp16) = 49152
#define SM_X0  49152     // x tile buffer 0: 256 x 256B = 65536
#define SM_X1  114688    // x tile buffer 1
#define SM_C   180224    // cst[32] + bm[4][32] floats = 640
#define SM_P   180864    // sP: 2 x 512 float2 = 8192
#define SMEM_TOTAL 189056

// ---- helpers --------------------------------------------------------------
__device__ __forceinline__ uint32_t h2pack(float a, float b) {
    __half2 h = __floats2half2_rn(a, b);
    return *(uint32_t*)&h;
}
__device__ __forceinline__ uint32_t smem_u32(const void* p) {
    uint32_t a;
    asm("{ .reg .u64 t; cvta.to.shared.u64 t, %1; cvt.u32.u64 %0, t; }" : "=r"(a) : "l"(p));
    return a;
}
__device__ __forceinline__ void mma16816(float c[4], const uint32_t a[4],
                                         uint32_t b0, uint32_t b1) {
    asm volatile(
        "mma.sync.aligned.m16n8k16.row.col.f32.f16.f16.f32 "
        "{%0,%1,%2,%3}, {%4,%5,%6,%7}, {%8,%9}, {%0,%1,%2,%3};"
        : "+f"(c[0]), "+f"(c[1]), "+f"(c[2]), "+f"(c[3])
        : "r"(a[0]), "r"(a[1]), "r"(a[2]), "r"(a[3]), "r"(b0), "r"(b1));
}
__device__ __forceinline__ void mma16816h(uint32_t c[2], const uint32_t a[4],
                                          uint32_t b0, uint32_t b1) {
    asm volatile(
        "mma.sync.aligned.m16n8k16.row.col.f16.f16.f16.f16 "
        "{%0,%1}, {%2,%3,%4,%5}, {%6,%7}, {%0,%1};"
        : "+r"(c[0]), "+r"(c[1])
        : "r"(a[0]), "r"(a[1]), "r"(a[2]), "r"(a[3]), "r"(b0), "r"(b1));
}
__device__ __forceinline__ void ldsm4(uint32_t r[4], uint32_t addr) {
    asm volatile("ldmatrix.sync.aligned.m8n8.x4.shared.b16 {%0,%1,%2,%3}, [%4];"
        : "=r"(r[0]), "=r"(r[1]), "=r"(r[2]), "=r"(r[3]) : "r"(addr));
}
__device__ __forceinline__ uint32_t sq2(uint32_t a) {
    __half2 h = *(__half2*)&a;
    h = __hmul2(h, h);
    return *(uint32_t*)&h;
}

// write one fp16 weight into the swizzled smem W tile
__device__ __forceinline__ void put_w(char* smc, int row, int d, float v) {
    const int sg = d >> 3;
    const uint32_t off = (uint32_t)(row * 256 + ((sg ^ (row & 7)) << 4) + (d & 7) * 2);
    *(__half*)(smc + SM_W + off) = __float2half_rn(v);
}

// ---------------------------------------------------------------------------
// Inline per-component precompute: one warp, one component k.
// Same verified fp32 warp-reduce math as R5-R11; writes weights (swizzled
// fp16) + cst/bm straight into this CTA's smem.
// ---------------------------------------------------------------------------
__device__ void precompute_comp(char* smc, int k, int lane,
                                const float* __restrict__ MU,
                                const float* __restrict__ A,
                                const float* __restrict__ Dm,
                                const float* __restrict__ PI)
{
    float s[22];
#pragma unroll
    for (int j = 0; j < 22; j++) s[j] = 0.f;

#pragma unroll
    for (int i = 0; i < 4; i++) {
        const int d = lane + 32 * i;
        const float Dv = Dm[k * DDIM + d];
        const float iD = 1.0f / (Dv * Dv);
        const float mu = MU[k * DDIM + d];
        float a[LDIM], B[LDIM];
#pragma unroll
        for (int l = 0; l < LDIM; l++) {
            a[l] = A[(k * DDIM + d) * LDIM + l];
            B[l] = iD * a[l];
        }
        int idx = 0;
#pragma unroll
        for (int l = 0; l < LDIM; l++)
#pragma unroll
            for (int m = 0; m < LDIM; m++)
                s[idx++] += a[l] * B[m];
#pragma unroll
        for (int m = 0; m < LDIM; m++)
            s[idx++] += mu * B[m];
        s[20] += iD * mu * mu;
        s[21] += 2.0f * logf(Dv);
    }

#pragma unroll
    for (int j = 0; j < 22; j++)
#pragma unroll
        for (int o = 16; o; o >>= 1)
            s[j] += __shfl_xor_sync(0xffffffffu, s[j], o);

    float Lm[LDIM][LDIM], bmu[LDIM];
#pragma unroll
    for (int l = 0; l < LDIM; l++)
#pragma unroll
        for (int m = 0; m < LDIM; m++)
            Lm[l][m] = s[l * LDIM + m] + (l == m ? 1.0f : 0.0f);
#pragma unroll
    for (int m = 0; m < LDIM; m++) bmu[m] = s[16 + m];
    const float tc  = s[20];
    const float sld = s[21];

    float G[LDIM][LDIM] = {};
#pragma unroll
    for (int i = 0; i < LDIM; i++) {
#pragma unroll
        for (int j = 0; j <= i; j++) {
            float v = Lm[i][j];
#pragma unroll
            for (int p = 0; p < LDIM; p++)
                if (p < j) v -= G[i][p] * G[j][p];
            if (i == j) G[i][i] = sqrtf(v);
            else        G[i][j] = v / G[j][j];
        }
    }
    float logdetL = 0.f;
#pragma unroll
    for (int i = 0; i < LDIM; i++) logdetL += 2.0f * logf(G[i][i]);

    float U[LDIM][LDIM] = {};
#pragma unroll
    for (int j = 0; j < LDIM; j++) {
        U[j][j] = 1.0f / G[j][j];
#pragma unroll
        for (int i = 0; i < LDIM; i++) {
            if (i > j) {
                float v = 0.f;
#pragma unroll
                for (int p = 0; p < LDIM; p++)
                    if (p >= j && p < i) v += G[i][p] * U[p][j];
                U[i][j] = -v / G[i][i];
            }
        }
    }

    if (lane == 0) {
        float* c = (float*)(smc + SM_C);
        const float LOG2PI = 1.8378770664093454835606594728112f;
        c[k] = PI[k] - 0.5f * ((float)DDIM * LOG2PI + logdetL + sld + tc);
        float bp[LDIM];
#pragma unroll
        for (int l = 0; l < LDIM; l++) {
            float v = 0.f;
#pragma unroll
            for (int m = 0; m <= l; m++) v += U[l][m] * bmu[m];
            bp[l] = v;
        }
        c[32 + k]  = bp[0]; c[64 + k]  = bp[1];
        c[96 + k]  = bp[2]; c[128 + k] = bp[3];
    }

#pragma unroll
    for (int i = 0; i < 4; i++) {
        const int d = lane + 32 * i;
        const float Dv = Dm[k * DDIM + d];
        const float iD = 1.0f / (Dv * Dv);
        const float mu = MU[k * DDIM + d];
        float B[LDIM];
#pragma unroll
        for (int l = 0; l < LDIM; l++)
            B[l] = iD * A[(k * DDIM + d) * LDIM + l];
        float Bp[LDIM];
#pragma unroll
        for (int l = 0; l < LDIM; l++) {
            float v = 0.f;
#pragma unroll
            for (int m = 0; m <= l; m++) v += U[l][m] * B[m];
            Bp[l] = v;
        }
        put_w(smc, k, d, iD * mu);
#pragma unroll
        for (int j = 0; j < LDIM; j++)
            put_w(smc, 32 + 32 * j + k, d, Bp[j]);
        put_w(smc, 160 + k, d, -0.5f * iD);
    }
}

// ---------------------------------------------------------------------------
// Single persistent kernel: inline precompute, then 256-row-tile GEMM loop.
// 16 warps = (wm 0-7, 32 rows each) x (wk 0-1, 16 comps).
// z accumulators fp16; staging in 4 batches of 2 LDG.128, constant-offset.
// ---------------------------------------------------------------------------
__global__ void __launch_bounds__(TPB, 1)
mfa_mma(const float* __restrict__ x, float* __restrict__ out, int N, int ntiles,
        const float* __restrict__ MU, const float* __restrict__ A,
        const float* __restrict__ Dm, const float* __restrict__ PI)
{
    extern __shared__ char smc[];
    const int tid  = threadIdx.x;
    const int lane = tid & 31;
    const int w    = tid >> 5;
    const int wm   = w & 7;         // row group (32 rows)
    const int wk   = w >> 3;        // component half (16 comps)
    const int qr   = lane >> 2;     // 0..7
    const int qc   = lane & 3;      // 0..3
    const int rin  = lane & 7;
    const int mat  = lane >> 3;     // 0..3

    const uint32_t sb = smem_u32(smc);

    // ---- inline precompute: warp w handles components 2w, 2w+1 ------------
    precompute_comp(smc, 2 * w,     lane, MU, A, Dm, PI);
    precompute_comp(smc, 2 * w + 1, lane, MU, A, Dm, PI);

    const float* cst = (const float*)(smc + SM_C);
    const uint32_t b_pre = sb + SM_W
        + (uint32_t)(wk * 16 + (mat >> 1) * 8 + rin) * 256u;
    uint32_t a_off[2];
#pragma unroll
    for (int mt = 0; mt < 2; mt++)
        a_off[mt] = (uint32_t)(wm * 32 + mt * 16 + (mat & 1) * 8 + rin) * 256u;

    // staging constants: slot j (0..7) -> row = base_r + 32j, off = base_off + 8192j
    const int base_r  = tid >> 4;
    const int st_s    = tid & 15;
    const uint32_t base_off =
        (uint32_t)(base_r * 256 + ((st_s ^ (base_r & 7)) << 4));

    // ---- prologue: load first tile into buffer 0 --------------------------
    {
        const int row0 = blockIdx.x * ROWS_TILE;
#pragma unroll
        for (int j = 0; j < 8; j++) {
            int row = row0 + base_r + 32 * j;
            row = row < N ? row : N - 1;
            const float4* p = (const float4*)x + (size_t)row * 32 + st_s * 2;
            const float4 v0 = __ldg(p), v1 = __ldg(p + 1);
            uint4 hx;
            hx.x = h2pack(v0.x, v0.y); hx.y = h2pack(v0.z, v0.w);
            hx.z = h2pack(v1.x, v1.y); hx.w = h2pack(v1.z, v1.w);
            *(uint4*)(smc + SM_X0 + base_off + 8192u * j) = hx;
        }
    }
    __syncthreads();

    int buf = 0;
    for (int tile = blockIdx.x; tile < ntiles; tile += gridDim.x) {
        const int row0 = tile * ROWS_TILE;
        const uint32_t xb_base = sb + (buf ? SM_X1 : SM_X0);
        char* nxt = smc + (buf ? SM_X0 : SM_X1);
        const int row0n = row0 + gridDim.x * ROWS_TILE;

        // staged pair (2 x float4 = 8 regs)
        float4 sv0, sv1;
        {
            int row = row0n + base_r;
            row = row < N ? row : N - 1;
            const float4* p = (const float4*)x + (size_t)row * 32 + st_s * 2;
            sv0 = __ldg(p); sv1 = __ldg(p + 1);
        }

        // ---- GEMM: accS fp32 (s2 + folded s1); accZ fp16 (z groups) -------
        float    accS[2][2][4];
        uint32_t accZ[2][4][2][2];
#pragma unroll
        for (int mt = 0; mt < 2; mt++) {
#pragma unroll
            for (int hi = 0; hi < 2; hi++)
#pragma unroll
                for (int e = 0; e < 4; e++) accS[mt][hi][e] = 0.f;
#pragma unroll
            for (int jj = 0; jj < 4; jj++)
#pragma unroll
                for (int hi = 0; hi < 2; hi++) {
                    accZ[mt][jj][hi][0] = 0u;
                    accZ[mt][jj][hi][1] = 0u;
                }
        }

#pragma unroll
        for (int ch = 0; ch < 8; ch++) {
            const uint32_t xa = (((uint32_t)(ch * 2 + (mat >> 1))) ^ (uint32_t)rin) << 4;
            const uint32_t xb = (((uint32_t)(ch * 2 + (mat & 1)))  ^ (uint32_t)rin) << 4;

            uint32_t ax[2][4];
            ldsm4(ax[0], xb_base + a_off[0] + xa);
            ldsm4(ax[1], xb_base + a_off[1] + xa);

            // g0: s2 (fp32 acc)
            {
                uint32_t b[4];
                ldsm4(b, b_pre + xb);
                mma16816(accS[0][0], ax[0], b[0], b[1]);
                mma16816(accS[0][1], ax[0], b[2], b[3]);
                mma16816(accS[1][0], ax[1], b[0], b[1]);
                mma16816(accS[1][1], ax[1], b[2], b[3]);
            }
            // z groups (fp16 acc)
#pragma unroll
            for (int jj = 0; jj < 4; jj++) {
                uint32_t b[4];
                ldsm4(b, b_pre + (uint32_t)(1 + jj) * 8192u + xb);
                mma16816h(accZ[0][jj][0], ax[0], b[0], b[1]);
                mma16816h(accZ[0][jj][1], ax[0], b[2], b[3]);
                mma16816h(accZ[1][jj][0], ax[1], b[0], b[1]);
                mma16816h(accZ[1][jj][1], ax[1], b[2], b[3]);
            }
            // s1 folded (-0.5*iD weights), fp32 acc into accS
            {
                uint32_t aq[2][4];
#pragma unroll
                for (int j = 0; j < 4; j++) {
                    aq[0][j] = sq2(ax[0][j]);
                    aq[1][j] = sq2(ax[1][j]);
                }
                uint32_t b[4];
                ldsm4(b, b_pre + 5u * 8192u + xb);
                mma16816(accS[0][0], aq[0], b[0], b[1]);
                mma16816(accS[0][1], aq[0], b[2], b[3]);
                mma16816(accS[1][0], aq[1], b[0], b[1]);
                mma16816(accS[1][1], aq[1], b[2], b[3]);
            }

            // staging: drain current pair, issue next pair (slots 2 per step)
            if ((ch & 1) && ch < 8) {
                const int b0 = ch >> 1;              // batch 0..3 at ch=1,3,5,7
                {
                    uint4 hx;
                    hx.x = h2pack(sv0.x, sv0.y); hx.y = h2pack(sv0.z, sv0.w);
                    hx.z = h2pack(sv1.x, sv1.y); hx.w = h2pack(sv1.z, sv1.w);
                    *(uint4*)(nxt + base_off + 8192u * (2 * b0)) = hx;
                }
                {
                    int row = row0n + base_r + 32 * (2 * b0 + 1);
                    row = row < N ? row : N - 1;
                    const float4* p = (const float4*)x + (size_t)row * 32 + st_s * 2;
                    const float4 v0 = __ldg(p), v1 = __ldg(p + 1);
                    uint4 hx;
                    hx.x = h2pack(v0.x, v0.y); hx.y = h2pack(v0.z, v0.w);
                    hx.z = h2pack(v1.x, v1.y); hx.w = h2pack(v1.z, v1.w);
                    *(uint4*)(nxt + base_off + 8192u * (2 * b0 + 1)) = hx;
                }
                if (b0 < 3) {
                    int row = row0n + base_r + 32 * (2 * b0 + 2);
                    row = row < N ? row : N - 1;
                    const float4* p = (const float4*)x + (size_t)row * 32 + st_s * 2;
                    sv0 = __ldg(p); sv1 = __ldg(p + 1);
                }
            }
        }

        // ---- partial epilogue: common max, then exp ------------------------
        float2* sP = (float2*)(smc + SM_P + (buf ? 4096 : 0));
#pragma unroll
        for (int mt = 0; mt < 2; mt++) {
#pragma unroll
            for (int h = 0; h < 2; h++) {
                float ll[4];
#pragma unroll
                for (int hi = 0; hi < 2; hi++) {
#pragma unroll
                    for (int p = 0; p < 2; p++) {
                        const int k = wk * 16 + hi * 8 + 2 * qc + p;
                        const int e = 2 * h + p;
                        float v = cst[k] + accS[mt][hi][e];
#pragma unroll
                        for (int jj = 0; jj < 4; jj++) {
                            const __half2 hz = *(const __half2*)&accZ[mt][jj][hi][h];
                            const float2 fz = __half22float2(hz);
                            const float z = (p ? fz.y : fz.x)
                                          - cst[32 + 32 * jj + k];
                            v = fmaf(0.5f * z, z, v);
                        }
                        ll[hi * 2 + p] = v;
                    }
                }
                float mx = fmaxf(fmaxf(ll[0], ll[1]), fmaxf(ll[2], ll[3]));
#pragma unroll
                for (int off = 1; off <= 2; off <<= 1)
                    mx = fmaxf(mx, __shfl_xor_sync(0xffffffffu, mx, off));
                float sum = __expf(ll[0] - mx) + __expf(ll[1] - mx)
                          + __expf(ll[2] - mx) + __expf(ll[3] - mx);
#pragma unroll
                for (int off = 1; off <= 2; off <<= 1)
                    sum += __shfl_xor_sync(0xffffffffu, sum, off);

                if (qc == 0)
                    sP[wk * 256 + wm * 32 + mt * 16 + qr + 8 * h]
                        = make_float2(mx, sum);
            }
        }
        __syncthreads();   // covers: sP writes, next-buffer STS, cur-buffer reads

        // ---- combine the two component halves, write out ------------------
        if (tid < 256) {
            const float2 a = sP[tid];
            const float2 b = sP[256 + tid];
            const float m = fmaxf(a.x, b.x);
            const float s = a.y * __expf(a.x - m) + b.y * __expf(b.x - m);
            const int row = row0 + tid;
            if (row < N) out[row] = m + __logf(s);
        }
        buf ^= 1;
    }
}

// ---------------------------------------------------------------------------
extern "C" void kernel_launch(void* const* d_in, const int* in_sizes, int n_in,
                              void* d_out, int out_size)
{
    const float* x  = (const float*)d_in[0];
    const float* MU = (const float*)d_in[1];
    const float* A  = (const float*)d_in[2];
    const float* Dm = (const float*)d_in[3];
    const float* PI = (const float*)d_in[4];
    float* out = (float*)d_out;

    const int N = in_sizes[0] / DDIM;
    const int ntiles = (N + ROWS_TILE - 1) / ROWS_TILE;

    int nsm = 148;
    cudaDeviceGetAttribute(&nsm, cudaDevAttrMultiProcessorCount, 0);
    if (nsm <= 0) nsm = 148;
    int grid = nsm < ntiles ? nsm : ntiles;

    cudaFuncSetAttribute(mfa_mma, cudaFuncAttributeMaxDynamicSharedMemorySize,
                         SMEM_TOTAL);

    mfa_mma<<<grid, TPB, SMEM_TOTAL>>>(x, out, N, ntiles, MU, A, Dm, PI);
}